// round 1
// baseline (speedup 1.0000x reference)
#include <cuda_runtime.h>
#include <math.h>

#define BB 8
#define NN 1024
#define EE 16384
#define FF 96
#define FE 32
#define HH 12
#define DD 8
#define KM 224           // 2F + Fe
#define KMP 228          // padded stride (mod 32 == 4 -> conflict-free LDS.128)
#define K2 192           // 2F
#define K2P 196
#define LN_EPS 1e-3f

// ---------------- scratch (no allocations allowed) ----------------
__device__ float g_agg [BB*NN*FF];
__device__ float g_q   [BB*HH*NN*DD];
__device__ float g_k   [BB*HH*NN*DD];
__device__ float g_v   [BB*HH*NN*DD];
__device__ float g_gate[BB*HH*NN*DD];
__device__ float g_att [BB*NN*FF];

__device__ __forceinline__ float gelu_erf(float x){
    return 0.5f * x * (1.0f + erff(x * 0.70710678118654752f));
}

// ---------------- helpers ----------------
__global__ void zero_agg_kernel(){
    int i = blockIdx.x*blockDim.x + threadIdx.x;
    if (i < BB*NN*FF) g_agg[i] = 0.0f;
}

__global__ void passthrough_kernel(const int* __restrict__ edges,
                                   const float* __restrict__ ew,
                                   const float* __restrict__ ed,
                                   float* __restrict__ out_edges,
                                   float* __restrict__ out_ew,
                                   float* __restrict__ out_ed){
    int i = blockIdx.x*blockDim.x + threadIdx.x;
    if (i < BB*EE*2){ out_edges[i] = (float)edges[i]; out_ed[i] = ed[i]; }
    if (i < BB*EE)  out_ew[i] = ew[i];
}

// ---------------- messages: LN(GELU([src,dst,ef] @ Wm + bm)) * w, scatter-add ----------------
__global__ void msg_kernel(const float* __restrict__ nodes, const float* __restrict__ efeat,
                           const int* __restrict__ edges, const float* __restrict__ ew,
                           const float* __restrict__ ed, const float* __restrict__ Wm,
                           const float* __restrict__ bm, const float* __restrict__ gm,
                           const float* __restrict__ betam, float* __restrict__ out_wm){
    extern __shared__ float smem[];
    float* sW  = smem;               // [96][KMP] transposed (col-major over k), padded
    float* sb  = sW + FF*KMP;        // 96
    float* sg  = sb + FF;
    float* sbe = sg + FF;
    float* sx  = sbe + FF;           // 8 warps * 4 edges * 224
    int tid = threadIdx.x;
    for (int i = tid; i < KM*FF; i += blockDim.x){
        int k = i / FF, c = i % FF;
        sW[c*KMP + k] = Wm[i];
    }
    if (tid < FF){ sb[tid]=bm[tid]; sg[tid]=gm[tid]; sbe[tid]=betam[tid]; }
    __syncthreads();

    int warp = tid >> 5, lane = tid & 31;
    float* x = sx + warp*(4*KM);
    int warpGlobal = blockIdx.x*8 + warp;

    for (int base = warpGlobal*4; base < BB*EE; base += gridDim.x*32){
        int dsts[4];
        #pragma unroll
        for (int e = 0; e < 4; e++){
            int eid = base + e;
            int b = eid >> 14;                  // E = 16384
            int src = edges[2*eid];
            int dst = edges[2*eid+1];
            dsts[e] = (b << 10) + dst;          // b*N + dst
            const float* ns = nodes + ((size_t)((b<<10) + src))*FF;
            const float* nd = nodes + ((size_t)((b<<10) + dst))*FF;
            const float* ep = efeat + (size_t)eid*FE;
            float* xe = x + e*KM;
            for (int i = lane; i < FF; i += 32){ xe[i] = ns[i]; xe[FF+i] = nd[i]; }
            xe[2*FF + lane] = ep[lane];
        }
        __syncwarp();

        float acc[3][4];
        #pragma unroll
        for (int c = 0; c < 3; c++){
            float bv = sb[lane + 32*c];
            #pragma unroll
            for (int e = 0; e < 4; e++) acc[c][e] = bv;
        }
        #pragma unroll 2
        for (int k = 0; k < KM; k += 4){
            float4 w0 = *(const float4*)(sW + (size_t)lane*KMP + k);
            float4 w1 = *(const float4*)(sW + (size_t)(lane+32)*KMP + k);
            float4 w2 = *(const float4*)(sW + (size_t)(lane+64)*KMP + k);
            #pragma unroll
            for (int e = 0; e < 4; e++){
                float4 xv = *(const float4*)(x + e*KM + k);
                acc[0][e] = fmaf(xv.x, w0.x, acc[0][e]); acc[0][e] = fmaf(xv.y, w0.y, acc[0][e]);
                acc[0][e] = fmaf(xv.z, w0.z, acc[0][e]); acc[0][e] = fmaf(xv.w, w0.w, acc[0][e]);
                acc[1][e] = fmaf(xv.x, w1.x, acc[1][e]); acc[1][e] = fmaf(xv.y, w1.y, acc[1][e]);
                acc[1][e] = fmaf(xv.z, w1.z, acc[1][e]); acc[1][e] = fmaf(xv.w, w1.w, acc[1][e]);
                acc[2][e] = fmaf(xv.x, w2.x, acc[2][e]); acc[2][e] = fmaf(xv.y, w2.y, acc[2][e]);
                acc[2][e] = fmaf(xv.z, w2.z, acc[2][e]); acc[2][e] = fmaf(xv.w, w2.w, acc[2][e]);
            }
        }
        __syncwarp();

        #pragma unroll
        for (int e = 0; e < 4; e++){
            int eid = base + e;
            float a0 = gelu_erf(acc[0][e]);
            float a1 = gelu_erf(acc[1][e]);
            float a2 = gelu_erf(acc[2][e]);
            float s = a0 + a1 + a2;
            #pragma unroll
            for (int off = 16; off; off >>= 1) s += __shfl_xor_sync(0xffffffffu, s, off);
            float mu = s * (1.0f/96.0f);
            float d0 = a0-mu, d1 = a1-mu, d2 = a2-mu;
            float ssq = d0*d0 + d1*d1 + d2*d2;
            #pragma unroll
            for (int off = 16; off; off >>= 1) ssq += __shfl_xor_sync(0xffffffffu, ssq, off);
            float r = rsqrtf(ssq * (1.0f/96.0f) + LN_EPS);
            float w  = ew[eid];
            float dr = ed[2*eid+1];
            float y0 = (d0*r*sg[lane]    + sbe[lane])    * w;
            float y1 = (d1*r*sg[lane+32] + sbe[lane+32]) * w;
            float y2 = (d2*r*sg[lane+64] + sbe[lane+64]) * w;
            float* ow = out_wm + (size_t)eid*FF;
            ow[lane] = y0; ow[lane+32] = y1; ow[lane+64] = y2;
            float* ap = g_agg + (size_t)dsts[e]*FF;
            atomicAdd(ap+lane,    y0*dr);
            atomicAdd(ap+lane+32, y1*dr);
            atomicAdd(ap+lane+64, y2*dr);
        }
        __syncwarp();
    }
}

// ---------------- q/k/v/gate projections: [nodes,agg] (192) -> 96, head layout ----------------
__global__ void qkvg_kernel(const float* __restrict__ nodes,
    const float* __restrict__ Wq, const float* __restrict__ bq,
    const float* __restrict__ Wk, const float* __restrict__ bk,
    const float* __restrict__ Wv, const float* __restrict__ bv,
    const float* __restrict__ Wg, const float* __restrict__ bg){
    extern __shared__ float smem[];
    float* sA  = smem;               // [96][K2P]
    float* sB  = sA + FF*K2P;        // [96][K2P]
    float* sbA = sB + FF*K2P;        // 96
    float* sbB = sbA + FF;           // 96
    float* sx  = sbB + FF;           // 8*4*192
    int pairI = blockIdx.y;          // 0: (q,k)  1: (v,gate)
    const float* WA = pairI ? Wv : Wq;
    const float* WB = pairI ? Wg : Wk;
    const float* bA = pairI ? bv : bq;
    const float* bB = pairI ? bg : bk;
    float* outA = pairI ? g_v    : g_q;
    float* outB = pairI ? g_gate : g_k;

    int tid = threadIdx.x;
    for (int i = tid; i < K2*FF; i += blockDim.x){
        int k = i / FF, c = i % FF;
        sA[c*K2P + k] = WA[i];
        sB[c*K2P + k] = WB[i];
    }
    if (tid < FF){ sbA[tid] = bA[tid]; sbB[tid] = bB[tid]; }
    __syncthreads();

    int warp = tid>>5, lane = tid&31;
    float* x = sx + warp*(4*K2);
    int warpGlobal = blockIdx.x*8 + warp;

    for (int base = warpGlobal*4; base < BB*NN; base += gridDim.x*32){
        #pragma unroll
        for (int e = 0; e < 4; e++){
            int idx = base + e;
            const float* np = nodes + (size_t)idx*FF;
            const float* ap = g_agg + (size_t)idx*FF;
            float* xe = x + e*K2;
            for (int i = lane; i < FF; i += 32){ xe[i] = np[i]; xe[FF+i] = ap[i]; }
        }
        __syncwarp();

        float accA[3][4], accB[3][4];
        #pragma unroll
        for (int c = 0; c < 3; c++){
            float ba = sbA[lane + 32*c], bb = sbB[lane + 32*c];
            #pragma unroll
            for (int e = 0; e < 4; e++){ accA[c][e] = ba; accB[c][e] = bb; }
        }
        #pragma unroll 2
        for (int k = 0; k < K2; k += 4){
            float4 wa0 = *(const float4*)(sA + (size_t)lane*K2P + k);
            float4 wa1 = *(const float4*)(sA + (size_t)(lane+32)*K2P + k);
            float4 wa2 = *(const float4*)(sA + (size_t)(lane+64)*K2P + k);
            float4 wb0 = *(const float4*)(sB + (size_t)lane*K2P + k);
            float4 wb1 = *(const float4*)(sB + (size_t)(lane+32)*K2P + k);
            float4 wb2 = *(const float4*)(sB + (size_t)(lane+64)*K2P + k);
            #pragma unroll
            for (int e = 0; e < 4; e++){
                float4 xv = *(const float4*)(x + e*K2 + k);
                accA[0][e] = fmaf(xv.x,wa0.x,accA[0][e]); accA[0][e] = fmaf(xv.y,wa0.y,accA[0][e]);
                accA[0][e] = fmaf(xv.z,wa0.z,accA[0][e]); accA[0][e] = fmaf(xv.w,wa0.w,accA[0][e]);
                accA[1][e] = fmaf(xv.x,wa1.x,accA[1][e]); accA[1][e] = fmaf(xv.y,wa1.y,accA[1][e]);
                accA[1][e] = fmaf(xv.z,wa1.z,accA[1][e]); accA[1][e] = fmaf(xv.w,wa1.w,accA[1][e]);
                accA[2][e] = fmaf(xv.x,wa2.x,accA[2][e]); accA[2][e] = fmaf(xv.y,wa2.y,accA[2][e]);
                accA[2][e] = fmaf(xv.z,wa2.z,accA[2][e]); accA[2][e] = fmaf(xv.w,wa2.w,accA[2][e]);
                accB[0][e] = fmaf(xv.x,wb0.x,accB[0][e]); accB[0][e] = fmaf(xv.y,wb0.y,accB[0][e]);
                accB[0][e] = fmaf(xv.z,wb0.z,accB[0][e]); accB[0][e] = fmaf(xv.w,wb0.w,accB[0][e]);
                accB[1][e] = fmaf(xv.x,wb1.x,accB[1][e]); accB[1][e] = fmaf(xv.y,wb1.y,accB[1][e]);
                accB[1][e] = fmaf(xv.z,wb1.z,accB[1][e]); accB[1][e] = fmaf(xv.w,wb1.w,accB[1][e]);
                accB[2][e] = fmaf(xv.x,wb2.x,accB[2][e]); accB[2][e] = fmaf(xv.y,wb2.y,accB[2][e]);
                accB[2][e] = fmaf(xv.z,wb2.z,accB[2][e]); accB[2][e] = fmaf(xv.w,wb2.w,accB[2][e]);
            }
        }
        __syncwarp();

        bool isGate = (pairI == 1);
        #pragma unroll
        for (int e = 0; e < 4; e++){
            int idx = base + e;
            int b = idx >> 10, n = idx & (NN-1);
            #pragma unroll
            for (int c = 0; c < 3; c++){
                int col = lane + 32*c;
                int h = col >> 3, dl = col & 7;
                size_t off = ((size_t)(b*HH + h)*NN + n)*DD + dl;
                outA[off] = accA[c][e];
                float vB = accB[c][e];
                if (isGate) vB = 1.0f/(1.0f + expf(-vB));
                outB[off] = vB;
            }
        }
        __syncwarp();
    }
}

// ---------------- attention per (b,h): softmax(qK^T/sqrt(d)) V * gate ----------------
__global__ void attn_kernel(){
    extern __shared__ float smem[];
    float* sK = smem;            // [D][N] transposed
    float* sV = smem + DD*NN;    // [D][N]
    int bh = blockIdx.x;
    const float* kp = g_k + (size_t)bh*NN*DD;
    const float* vp = g_v + (size_t)bh*NN*DD;
    for (int i = threadIdx.x; i < NN*DD; i += blockDim.x){
        int j = i >> 3, d = i & 7;
        sK[d*NN + j] = kp[i];
        sV[d*NN + j] = vp[i];
    }
    __syncthreads();

    int warp = threadIdx.x>>5, lane = threadIdx.x&31;
    int b = bh / HH, h = bh % HH;
    int row0 = blockIdx.y * (NN/4);

    for (int row = row0 + warp; row < row0 + NN/4; row += 8){
        const float* qp = g_q + ((size_t)bh*NN + row)*DD;
        float q[DD];
        #pragma unroll
        for (int d = 0; d < DD; d++) q[d] = qp[d] * 0.35355339059327373f;  // 1/sqrt(8)

        float s[32];
        #pragma unroll
        for (int t = 0; t < 32; t++){
            int j = t*32 + lane;
            float acc = 0.0f;
            #pragma unroll
            for (int d = 0; d < DD; d++) acc = fmaf(q[d], sK[d*NN + j], acc);
            s[t] = acc;
        }
        float m = s[0];
        #pragma unroll
        for (int t = 1; t < 32; t++) m = fmaxf(m, s[t]);
        #pragma unroll
        for (int off = 16; off; off >>= 1) m = fmaxf(m, __shfl_xor_sync(0xffffffffu, m, off));
        float l = 0.0f;
        #pragma unroll
        for (int t = 0; t < 32; t++){ s[t] = expf(s[t] - m); l += s[t]; }
        #pragma unroll
        for (int off = 16; off; off >>= 1) l += __shfl_xor_sync(0xffffffffu, l, off);

        float o[DD];
        #pragma unroll
        for (int d = 0; d < DD; d++) o[d] = 0.0f;
        #pragma unroll
        for (int t = 0; t < 32; t++){
            int j = t*32 + lane;
            float p = s[t];
            #pragma unroll
            for (int d = 0; d < DD; d++) o[d] = fmaf(p, sV[d*NN + j], o[d]);
        }
        #pragma unroll
        for (int d = 0; d < DD; d++){
            #pragma unroll
            for (int off = 16; off; off >>= 1) o[d] += __shfl_xor_sync(0xffffffffu, o[d], off);
        }
        float inv = 1.0f / l;
        if (lane < DD){
            float gate = g_gate[((size_t)bh*NN + row)*DD + lane];
            g_att[((size_t)((b<<10) + row))*FF + h*DD + lane] = o[lane]*inv*gate;
        }
    }
}

// ---------------- output: LN(GELU(att @ Wo + bo)) ----------------
__global__ void out_kernel(const float* __restrict__ Wo, const float* __restrict__ bo,
                           const float* __restrict__ gu, const float* __restrict__ betau,
                           float* __restrict__ out){
    __shared__ float sW[FF*FF];
    __shared__ float sb[FF], sg[FF], sbe[FF];
    __shared__ float sx[8*FF];
    int tid = threadIdx.x;
    for (int i = tid; i < FF*FF; i += blockDim.x) sW[i] = Wo[i];
    if (tid < FF){ sb[tid]=bo[tid]; sg[tid]=gu[tid]; sbe[tid]=betau[tid]; }
    __syncthreads();

    int warp = tid>>5, lane = tid&31;
    float* x = sx + warp*FF;
    for (int idx = blockIdx.x*8 + warp; idx < BB*NN; idx += gridDim.x*8){
        const float* ap = g_att + (size_t)idx*FF;
        for (int i = lane; i < FF; i += 32) x[i] = ap[i];
        __syncwarp();
        float a0 = sb[lane], a1 = sb[lane+32], a2 = sb[lane+64];
        #pragma unroll 4
        for (int k = 0; k < FF; k++){
            float xv = x[k];
            a0 = fmaf(xv, sW[k*FF+lane],    a0);
            a1 = fmaf(xv, sW[k*FF+lane+32], a1);
            a2 = fmaf(xv, sW[k*FF+lane+64], a2);
        }
        a0 = gelu_erf(a0); a1 = gelu_erf(a1); a2 = gelu_erf(a2);
        float s = a0 + a1 + a2;
        #pragma unroll
        for (int off = 16; off; off >>= 1) s += __shfl_xor_sync(0xffffffffu, s, off);
        float mu = s * (1.0f/96.0f);
        float d0 = a0-mu, d1 = a1-mu, d2 = a2-mu;
        float ssq = d0*d0 + d1*d1 + d2*d2;
        #pragma unroll
        for (int off = 16; off; off >>= 1) ssq += __shfl_xor_sync(0xffffffffu, ssq, off);
        float r = rsqrtf(ssq * (1.0f/96.0f) + LN_EPS);
        float* op = out + (size_t)idx*FF;
        op[lane]    = d0*r*sg[lane]    + sbe[lane];
        op[lane+32] = d1*r*sg[lane+32] + sbe[lane+32];
        op[lane+64] = d2*r*sg[lane+64] + sbe[lane+64];
        __syncwarp();
    }
}

// ---------------- launch ----------------
extern "C" void kernel_launch(void* const* d_in, const int* in_sizes, int n_in,
                              void* d_out, int out_size){
    const float* nodes = (const float*)d_in[0];
    const float* efeat = (const float*)d_in[1];
    const int*   edges = (const int*)  d_in[2];
    const float* ew    = (const float*)d_in[3];
    const float* ed    = (const float*)d_in[4];
    const float* Wm    = (const float*)d_in[5];
    const float* bm    = (const float*)d_in[6];
    const float* gm    = (const float*)d_in[7];
    const float* betam = (const float*)d_in[8];
    const float* Wq=(const float*)d_in[9],  *bq=(const float*)d_in[10];
    const float* Wk=(const float*)d_in[11], *bk=(const float*)d_in[12];
    const float* Wv=(const float*)d_in[13], *bv=(const float*)d_in[14];
    const float* Wg=(const float*)d_in[15], *bg=(const float*)d_in[16];
    const float* Wo=(const float*)d_in[17], *bo=(const float*)d_in[18];
    const float* gu=(const float*)d_in[19], *betau=(const float*)d_in[20];
    float* out = (float*)d_out;

    // output layout: [updated_nodes | weighted_messages | edges(f32) | edge_weights | edge_dropout]
    const size_t OFF_WM    = (size_t)BB*NN*FF;                 // 786432
    const size_t OFF_EDGES = OFF_WM + (size_t)BB*EE*FF;        // +12582912
    const size_t OFF_EW    = OFF_EDGES + (size_t)BB*EE*2;
    const size_t OFF_ED    = OFF_EW + (size_t)BB*EE;

    const int MSG_SMEM  = (FF*KMP + 3*FF + 8*4*KM)*4;          // 117376 B
    const int QKVG_SMEM = (2*FF*K2P + 2*FF + 8*4*K2)*4;        // 175872 B
    const int ATTN_SMEM = 2*NN*DD*4;                           // 65536 B
    cudaFuncSetAttribute(msg_kernel,  cudaFuncAttributeMaxDynamicSharedMemorySize, MSG_SMEM);
    cudaFuncSetAttribute(qkvg_kernel, cudaFuncAttributeMaxDynamicSharedMemorySize, QKVG_SMEM);
    cudaFuncSetAttribute(attn_kernel, cudaFuncAttributeMaxDynamicSharedMemorySize, ATTN_SMEM);

    zero_agg_kernel<<<(BB*NN*FF+255)/256, 256>>>();
    passthrough_kernel<<<(BB*EE*2+255)/256, 256>>>(edges, ew, ed,
                                                   out+OFF_EDGES, out+OFF_EW, out+OFF_ED);
    msg_kernel<<<1024, 256, MSG_SMEM>>>(nodes, efeat, edges, ew, ed,
                                        Wm, bm, gm, betam, out+OFF_WM);
    qkvg_kernel<<<dim3(256,2), 256, QKVG_SMEM>>>(nodes, Wq,bq, Wk,bk, Wv,bv, Wg,bg);
    attn_kernel<<<dim3(BB*HH,4), 256, ATTN_SMEM>>>();
    out_kernel<<<1024, 256>>>(Wo, bo, gu, betau, out);
}

// round 2
// speedup vs baseline: 1.7099x; 1.7099x over previous
#include <cuda_runtime.h>
#include <math.h>

#define BB 8
#define NN 1024
#define EE 16384
#define FF 96
#define FE 32
#define HH 12
#define DD 8
#define KM 224           // 2F + Fe
#define KMP 228          // padded stride: 228 % 32 == 4 -> conflict-free LDS.128
#define K2 192           // 2F
#define K2P 196
#define EPB 8            // rows/edges per warp per iteration
#define LN_EPS 1e-3f
#define ATT_SCALE 0.35355339059327373f

typedef unsigned long long u64;

// ---------------- packed f32x2 helpers ----------------
__device__ __forceinline__ u64 ffma2(u64 a, u64 b, u64 c){
    u64 d; asm("fma.rn.f32x2 %0, %1, %2, %3;" : "=l"(d) : "l"(a), "l"(b), "l"(c)); return d;
}
__device__ __forceinline__ u64 fmul2(u64 a, u64 b){
    u64 d; asm("mul.rn.f32x2 %0, %1, %2;" : "=l"(d) : "l"(a), "l"(b)); return d;
}
__device__ __forceinline__ u64 pack2(float a, float b){
    u64 r; asm("mov.b64 %0, {%1, %2};" : "=l"(r) : "f"(a), "f"(b)); return r;
}
__device__ __forceinline__ float2 unpack2(u64 v){
    float2 f; asm("mov.b64 {%0, %1}, %2;" : "=f"(f.x), "=f"(f.y) : "l"(v)); return f;
}
__device__ __forceinline__ float psum2(u64 v){ float2 f = unpack2(v); return f.x + f.y; }

__device__ __forceinline__ float gelu_erf(float x){
    return 0.5f * x * (1.0f + erff(x * 0.70710678118654752f));
}

// ---------------- scratch ----------------
__device__ float g_agg [BB*NN*FF];
__device__ float g_q   [BB*HH*NN*DD];
__device__ float g_k   [BB*HH*NN*DD];
__device__ float g_v   [BB*HH*NN*DD];
__device__ float g_gate[BB*HH*NN*DD];
__device__ float g_att [BB*NN*FF];

// ---------------- helpers ----------------
__global__ void zero_agg_kernel(){
    int i = blockIdx.x*blockDim.x + threadIdx.x;
    if (i < BB*NN*FF) g_agg[i] = 0.0f;
}

__global__ void passthrough_kernel(const int* __restrict__ edges,
                                   const float* __restrict__ ew,
                                   const float* __restrict__ ed,
                                   float* __restrict__ out_edges,
                                   float* __restrict__ out_ew,
                                   float* __restrict__ out_ed){
    int i = blockIdx.x*blockDim.x + threadIdx.x;
    if (i < BB*EE*2){ out_edges[i] = (float)edges[i]; out_ed[i] = ed[i]; }
    if (i < BB*EE)  out_ew[i] = ew[i];
}

// ---------------- messages ----------------
__global__ __launch_bounds__(256,1)
void msg_kernel(const float* __restrict__ nodes, const float* __restrict__ efeat,
                const int* __restrict__ edges, const float* __restrict__ ew,
                const float* __restrict__ ed, const float* __restrict__ Wm,
                const float* __restrict__ bm, const float* __restrict__ gm,
                const float* __restrict__ betam, float* __restrict__ out_wm){
    extern __shared__ float smem[];
    float* sW  = smem;               // [96][KMP] (col-major over k, padded)
    float* sb  = sW + FF*KMP;
    float* sg  = sb + FF;
    float* sbe = sg + FF;
    float* sx  = sbe + FF;           // 8 warps * EPB * 224
    int tid = threadIdx.x;
    for (int i = tid; i < KM*FF; i += blockDim.x){
        int k = i / FF, c = i % FF;
        sW[c*KMP + k] = Wm[i];
    }
    if (tid < FF){ sb[tid]=bm[tid]; sg[tid]=gm[tid]; sbe[tid]=betam[tid]; }
    __syncthreads();

    int warp = tid >> 5, lane = tid & 31;
    float* x = sx + warp*(EPB*KM);
    int warpGlobal = blockIdx.x*8 + warp;

    const ulonglong2* wp0 = (const ulonglong2*)(sW + (size_t)lane*KMP);
    const ulonglong2* wp1 = (const ulonglong2*)(sW + (size_t)(lane+32)*KMP);
    const ulonglong2* wp2 = (const ulonglong2*)(sW + (size_t)(lane+64)*KMP);

    for (int base = warpGlobal*EPB; base < BB*EE; base += gridDim.x*8*EPB){
        int dsts[EPB];
        #pragma unroll
        for (int e = 0; e < EPB; e++){
            int eid = base + e;
            int b = eid >> 14;
            int src = edges[2*eid];
            int dst = edges[2*eid+1];
            dsts[e] = (b << 10) + dst;
            const float4* ns = (const float4*)(nodes + ((size_t)((b<<10) + src))*FF);
            const float4* nd = (const float4*)(nodes + ((size_t)((b<<10) + dst))*FF);
            const float4* ep = (const float4*)(efeat + (size_t)eid*FE);
            float4* xe = (float4*)(x + e*KM);
            #pragma unroll
            for (int i0 = 0; i0 < 2; i0++){
                int i = lane + 32*i0;
                if (i < 56){
                    float4 v = (i < 24) ? ns[i] : ((i < 48) ? nd[i-24] : ep[i-48]);
                    xe[i] = v;
                }
            }
        }
        __syncwarp();

        u64 a0[EPB], a1[EPB], a2[EPB];
        #pragma unroll
        for (int e = 0; e < EPB; e++){ a0[e]=0ull; a1[e]=0ull; a2[e]=0ull; }

        #pragma unroll 4
        for (int ks = 0; ks < KM/4; ks++){
            ulonglong2 w0 = wp0[ks], w1 = wp1[ks], w2 = wp2[ks];
            #pragma unroll
            for (int e = 0; e < EPB; e++){
                ulonglong2 xv = ((const ulonglong2*)(x + e*KM))[ks];
                a0[e] = ffma2(xv.x, w0.x, a0[e]); a0[e] = ffma2(xv.y, w0.y, a0[e]);
                a1[e] = ffma2(xv.x, w1.x, a1[e]); a1[e] = ffma2(xv.y, w1.y, a1[e]);
                a2[e] = ffma2(xv.x, w2.x, a2[e]); a2[e] = ffma2(xv.y, w2.y, a2[e]);
            }
        }
        __syncwarp();

        #pragma unroll
        for (int e = 0; e < EPB; e++){
            int eid = base + e;
            float v0 = gelu_erf(psum2(a0[e]) + sb[lane]);
            float v1 = gelu_erf(psum2(a1[e]) + sb[lane+32]);
            float v2 = gelu_erf(psum2(a2[e]) + sb[lane+64]);
            float s = v0 + v1 + v2;
            #pragma unroll
            for (int off = 16; off; off >>= 1) s += __shfl_xor_sync(0xffffffffu, s, off);
            float mu = s * (1.0f/96.0f);
            float d0 = v0-mu, d1 = v1-mu, d2 = v2-mu;
            float ssq = d0*d0 + d1*d1 + d2*d2;
            #pragma unroll
            for (int off = 16; off; off >>= 1) ssq += __shfl_xor_sync(0xffffffffu, ssq, off);
            float r = rsqrtf(ssq * (1.0f/96.0f) + LN_EPS);
            float w  = ew[eid];
            float dr = ed[2*eid+1];
            float y0 = (d0*r*sg[lane]    + sbe[lane])    * w;
            float y1 = (d1*r*sg[lane+32] + sbe[lane+32]) * w;
            float y2 = (d2*r*sg[lane+64] + sbe[lane+64]) * w;
            float* ow = out_wm + (size_t)eid*FF;
            ow[lane] = y0; ow[lane+32] = y1; ow[lane+64] = y2;
            float* ap = g_agg + (size_t)dsts[e]*FF;
            atomicAdd(ap+lane,    y0*dr);
            atomicAdd(ap+lane+32, y1*dr);
            atomicAdd(ap+lane+64, y2*dr);
        }
        __syncwarp();
    }
}

// ---------------- q/k/v/gate projections (one matrix per blockIdx.y) ----------------
__global__ __launch_bounds__(256,1)
void qkvg_kernel(const float* __restrict__ nodes,
    const float* __restrict__ Wq, const float* __restrict__ bq,
    const float* __restrict__ Wk, const float* __restrict__ bk,
    const float* __restrict__ Wv, const float* __restrict__ bv,
    const float* __restrict__ Wg, const float* __restrict__ bg){
    extern __shared__ float smem[];
    float* sA  = smem;               // [96][K2P]
    float* sbA = sA + FF*K2P;        // 96
    float* sx  = sbA + FF;           // 8 warps * EPB * 192
    int m = blockIdx.y;
    const float* WA = (m==0)?Wq:((m==1)?Wk:((m==2)?Wv:Wg));
    const float* bA = (m==0)?bq:((m==1)?bk:((m==2)?bv:bg));
    float* outA     = (m==0)?g_q:((m==1)?g_k:((m==2)?g_v:g_gate));
    bool isGate = (m == 3);

    int tid = threadIdx.x;
    for (int i = tid; i < K2*FF; i += blockDim.x){
        int k = i / FF, c = i % FF;
        sA[c*K2P + k] = WA[i];
    }
    if (tid < FF) sbA[tid] = bA[tid];
    __syncthreads();

    int warp = tid>>5, lane = tid&31;
    float* x = sx + warp*(EPB*K2);
    int warpGlobal = blockIdx.x*8 + warp;

    const ulonglong2* wp0 = (const ulonglong2*)(sA + (size_t)lane*K2P);
    const ulonglong2* wp1 = (const ulonglong2*)(sA + (size_t)(lane+32)*K2P);
    const ulonglong2* wp2 = (const ulonglong2*)(sA + (size_t)(lane+64)*K2P);

    for (int base = warpGlobal*EPB; base < BB*NN; base += gridDim.x*8*EPB){
        #pragma unroll
        for (int e = 0; e < EPB; e++){
            int idx = base + e;
            const float4* np = (const float4*)(nodes + (size_t)idx*FF);
            const float4* ap = (const float4*)(g_agg + (size_t)idx*FF);
            float4* xe = (float4*)(x + e*K2);
            #pragma unroll
            for (int i0 = 0; i0 < 2; i0++){
                int i = lane + 32*i0;
                if (i < 48){
                    float4 v = (i < 24) ? np[i] : ap[i-24];
                    xe[i] = v;
                }
            }
        }
        __syncwarp();

        u64 a0[EPB], a1[EPB], a2[EPB];
        #pragma unroll
        for (int e = 0; e < EPB; e++){ a0[e]=0ull; a1[e]=0ull; a2[e]=0ull; }

        #pragma unroll 4
        for (int ks = 0; ks < K2/4; ks++){
            ulonglong2 w0 = wp0[ks], w1 = wp1[ks], w2 = wp2[ks];
            #pragma unroll
            for (int e = 0; e < EPB; e++){
                ulonglong2 xv = ((const ulonglong2*)(x + e*K2))[ks];
                a0[e] = ffma2(xv.x, w0.x, a0[e]); a0[e] = ffma2(xv.y, w0.y, a0[e]);
                a1[e] = ffma2(xv.x, w1.x, a1[e]); a1[e] = ffma2(xv.y, w1.y, a1[e]);
                a2[e] = ffma2(xv.x, w2.x, a2[e]); a2[e] = ffma2(xv.y, w2.y, a2[e]);
            }
        }
        __syncwarp();

        #pragma unroll
        for (int e = 0; e < EPB; e++){
            int idx = base + e;
            int b = idx >> 10, n = idx & (NN-1);
            float vals[3];
            vals[0] = psum2(a0[e]) + sbA[lane];
            vals[1] = psum2(a1[e]) + sbA[lane+32];
            vals[2] = psum2(a2[e]) + sbA[lane+64];
            #pragma unroll
            for (int c = 0; c < 3; c++){
                int col = lane + 32*c;
                int h = col >> 3, dl = col & 7;
                size_t off = ((size_t)(b*HH + h)*NN + n)*DD + dl;
                float v = vals[c];
                if (isGate) v = 1.0f/(1.0f + __expf(-v));
                outA[off] = v;
            }
        }
        __syncwarp();
    }
}

// ---------------- attention: K,V staged [N][10]; 4 rows/warp; 2-pass softmax ----------------
#define RPW 4
__global__ __launch_bounds__(256,2)
void attn_kernel(){
    extern __shared__ float smem[];
    float* sK = smem;                // [N][10] padded
    float* sV = smem + NN*10;
    int bh = blockIdx.x;
    int b = bh / HH, h = bh % HH;
    int tid = threadIdx.x;

    for (int j = tid; j < NN; j += 256){
        const ulonglong2* kr = (const ulonglong2*)(g_k + ((size_t)bh*NN + j)*DD);
        const ulonglong2* vr = (const ulonglong2*)(g_v + ((size_t)bh*NN + j)*DD);
        ulonglong2 k01 = kr[0], k23 = kr[1];
        ulonglong2 v01 = vr[0], v23 = vr[1];
        u64* kd = (u64*)(sK + (size_t)j*10);
        u64* vd = (u64*)(sV + (size_t)j*10);
        kd[0]=k01.x; kd[1]=k01.y; kd[2]=k23.x; kd[3]=k23.y;
        vd[0]=v01.x; vd[1]=v01.y; vd[2]=v23.x; vd[3]=v23.y;
    }
    __syncthreads();

    int warp = tid>>5, lane = tid&31;
    int rowBase = blockIdx.y*128 + warp*RPW;

    for (int p = 0; p < 4; p++){
        int r0 = rowBase + p*32;

        u64 q2[RPW][4];
        #pragma unroll
        for (int rr = 0; rr < RPW; rr++){
            const ulonglong2* qp = (const ulonglong2*)(g_q + ((size_t)bh*NN + r0+rr)*DD);
            ulonglong2 qa = qp[0], qb = qp[1];
            q2[rr][0]=qa.x; q2[rr][1]=qa.y; q2[rr][2]=qb.x; q2[rr][3]=qb.y;
        }

        // pass 1: exact row max (on unscaled scores; scale is positive/monotone)
        float mx[RPW];
        #pragma unroll
        for (int rr = 0; rr < RPW; rr++) mx[rr] = -3.4e38f;
        #pragma unroll 4
        for (int t = 0; t < 32; t++){
            int j = t*32 + lane;
            const u64* kj = (const u64*)(sK + (size_t)j*10);
            u64 k0=kj[0], k1=kj[1], k2=kj[2], k3=kj[3];
            #pragma unroll
            for (int rr = 0; rr < RPW; rr++){
                u64 acc = fmul2(q2[rr][0], k0);
                acc = ffma2(q2[rr][1], k1, acc);
                acc = ffma2(q2[rr][2], k2, acc);
                acc = ffma2(q2[rr][3], k3, acc);
                mx[rr] = fmaxf(mx[rr], psum2(acc));
            }
        }
        float msc[RPW];
        #pragma unroll
        for (int rr = 0; rr < RPW; rr++){
            #pragma unroll
            for (int off = 16; off; off >>= 1)
                mx[rr] = fmaxf(mx[rr], __shfl_xor_sync(0xffffffffu, mx[rr], off));
            msc[rr] = mx[rr] * ATT_SCALE;
        }

        // pass 2: exp + weighted V accumulation (d-packed)
        float l[RPW];
        u64 o2[RPW][4];
        #pragma unroll
        for (int rr = 0; rr < RPW; rr++){
            l[rr] = 0.0f;
            o2[rr][0]=o2[rr][1]=o2[rr][2]=o2[rr][3]=0ull;
        }
        #pragma unroll 2
        for (int t = 0; t < 32; t++){
            int j = t*32 + lane;
            const u64* kj = (const u64*)(sK + (size_t)j*10);
            const u64* vj = (const u64*)(sV + (size_t)j*10);
            u64 k0=kj[0], k1=kj[1], k2=kj[2], k3=kj[3];
            u64 v0=vj[0], v1=vj[1], v2=vj[2], v3=vj[3];
            #pragma unroll
            for (int rr = 0; rr < RPW; rr++){
                u64 acc = fmul2(q2[rr][0], k0);
                acc = ffma2(q2[rr][1], k1, acc);
                acc = ffma2(q2[rr][2], k2, acc);
                acc = ffma2(q2[rr][3], k3, acc);
                float s = psum2(acc);
                float pe = __expf(fmaf(s, ATT_SCALE, -msc[rr]));
                l[rr] += pe;
                u64 p2 = pack2(pe, pe);
                o2[rr][0] = ffma2(p2, v0, o2[rr][0]);
                o2[rr][1] = ffma2(p2, v1, o2[rr][1]);
                o2[rr][2] = ffma2(p2, v2, o2[rr][2]);
                o2[rr][3] = ffma2(p2, v3, o2[rr][3]);
            }
        }

        // reduce + write
        #pragma unroll
        for (int rr = 0; rr < RPW; rr++){
            #pragma unroll
            for (int off = 16; off; off >>= 1) l[rr] += __shfl_xor_sync(0xffffffffu, l[rr], off);
            float2 od[4];
            #pragma unroll
            for (int k = 0; k < 4; k++){
                u64 v = o2[rr][k];
                #pragma unroll
                for (int off = 16; off; off >>= 1){
                    u64 o = __shfl_xor_sync(0xffffffffu, v, off);
                    float2 va = unpack2(v), vb = unpack2(o);
                    v = pack2(va.x+vb.x, va.y+vb.y);
                }
                od[k] = unpack2(v);
            }
            if (lane < DD){
                float inv = 1.0f / l[rr];
                float val = (lane & 1) ? od[lane>>1].y : od[lane>>1].x;
                float gate = g_gate[((size_t)bh*NN + r0+rr)*DD + lane];
                g_att[((size_t)((b<<10) + r0+rr))*FF + h*DD + lane] = val*inv*gate;
            }
        }
    }
}

// ---------------- output: LN(GELU(att @ Wo + bo)) ----------------
__global__ void out_kernel(const float* __restrict__ Wo, const float* __restrict__ bo,
                           const float* __restrict__ gu, const float* __restrict__ betau,
                           float* __restrict__ out){
    __shared__ float sW[FF*FF];
    __shared__ float sb[FF], sg[FF], sbe[FF];
    __shared__ float sx[8*FF];
    int tid = threadIdx.x;
    for (int i = tid; i < FF*FF; i += blockDim.x) sW[i] = Wo[i];
    if (tid < FF){ sb[tid]=bo[tid]; sg[tid]=gu[tid]; sbe[tid]=betau[tid]; }
    __syncthreads();

    int warp = tid>>5, lane = tid&31;
    float* x = sx + warp*FF;
    for (int idx = blockIdx.x*8 + warp; idx < BB*NN; idx += gridDim.x*8){
        const float* ap = g_att + (size_t)idx*FF;
        for (int i = lane; i < FF; i += 32) x[i] = ap[i];
        __syncwarp();
        float a0 = sb[lane], a1 = sb[lane+32], a2 = sb[lane+64];
        #pragma unroll 4
        for (int k = 0; k < FF; k++){
            float xv = x[k];
            a0 = fmaf(xv, sW[k*FF+lane],    a0);
            a1 = fmaf(xv, sW[k*FF+lane+32], a1);
            a2 = fmaf(xv, sW[k*FF+lane+64], a2);
        }
        a0 = gelu_erf(a0); a1 = gelu_erf(a1); a2 = gelu_erf(a2);
        float s = a0 + a1 + a2;
        #pragma unroll
        for (int off = 16; off; off >>= 1) s += __shfl_xor_sync(0xffffffffu, s, off);
        float mu = s * (1.0f/96.0f);
        float d0 = a0-mu, d1 = a1-mu, d2 = a2-mu;
        float ssq = d0*d0 + d1*d1 + d2*d2;
        #pragma unroll
        for (int off = 16; off; off >>= 1) ssq += __shfl_xor_sync(0xffffffffu, ssq, off);
        float r = rsqrtf(ssq * (1.0f/96.0f) + LN_EPS);
        float* op = out + (size_t)idx*FF;
        op[lane]    = d0*r*sg[lane]    + sbe[lane];
        op[lane+32] = d1*r*sg[lane+32] + sbe[lane+32];
        op[lane+64] = d2*r*sg[lane+64] + sbe[lane+64];
        __syncwarp();
    }
}

// ---------------- launch ----------------
extern "C" void kernel_launch(void* const* d_in, const int* in_sizes, int n_in,
                              void* d_out, int out_size){
    const float* nodes = (const float*)d_in[0];
    const float* efeat = (const float*)d_in[1];
    const int*   edges = (const int*)  d_in[2];
    const float* ew    = (const float*)d_in[3];
    const float* ed    = (const float*)d_in[4];
    const float* Wm    = (const float*)d_in[5];
    const float* bm    = (const float*)d_in[6];
    const float* gm    = (const float*)d_in[7];
    const float* betam = (const float*)d_in[8];
    const float* Wq=(const float*)d_in[9],  *bq=(const float*)d_in[10];
    const float* Wk=(const float*)d_in[11], *bk=(const float*)d_in[12];
    const float* Wv=(const float*)d_in[13], *bv=(const float*)d_in[14];
    const float* Wg=(const float*)d_in[15], *bg=(const float*)d_in[16];
    const float* Wo=(const float*)d_in[17], *bo=(const float*)d_in[18];
    const float* gu=(const float*)d_in[19], *betau=(const float*)d_in[20];
    float* out = (float*)d_out;

    const size_t OFF_WM    = (size_t)BB*NN*FF;
    const size_t OFF_EDGES = OFF_WM + (size_t)BB*EE*FF;
    const size_t OFF_EW    = OFF_EDGES + (size_t)BB*EE*2;
    const size_t OFF_ED    = OFF_EW + (size_t)BB*EE;

    const int MSG_SMEM  = (FF*KMP + 3*FF + 8*EPB*KM)*4;   // 146048 B
    const int QKVG_SMEM = (FF*K2P + FF + 8*EPB*K2)*4;     // 124800 B
    const int ATTN_SMEM = 2*NN*10*4;                      // 81920 B
    cudaFuncSetAttribute(msg_kernel,  cudaFuncAttributeMaxDynamicSharedMemorySize, MSG_SMEM);
    cudaFuncSetAttribute(qkvg_kernel, cudaFuncAttributeMaxDynamicSharedMemorySize, QKVG_SMEM);
    cudaFuncSetAttribute(attn_kernel, cudaFuncAttributeMaxDynamicSharedMemorySize, ATTN_SMEM);

    zero_agg_kernel<<<(BB*NN*FF+255)/256, 256>>>();
    passthrough_kernel<<<(BB*EE*2+255)/256, 256>>>(edges, ew, ed,
                                                   out+OFF_EDGES, out+OFF_EW, out+OFF_ED);
    msg_kernel<<<148, 256, MSG_SMEM>>>(nodes, efeat, edges, ew, ed,
                                       Wm, bm, gm, betam, out+OFF_WM);
    qkvg_kernel<<<dim3(37,4), 256, QKVG_SMEM>>>(nodes, Wq,bq, Wk,bk, Wv,bv, Wg,bg);
    attn_kernel<<<dim3(BB*HH,8), 256, ATTN_SMEM>>>();
    out_kernel<<<1024, 256>>>(Wo, bo, gu, betau, out);
}

// round 6
// speedup vs baseline: 1.7173x; 1.0043x over previous
#include <cuda_runtime.h>
#include <math.h>

#define BB 8
#define NN 1024
#define EE 16384
#define FF 96
#define FE 32
#define HH 12
#define DD 8
#define KM 224           // 2F + Fe
#define KMP 228          // padded stride: conflict-free LDS.128
#define K2 192           // 2F
#define K2P 196
#define EPB 8            // rows/edges per warp per iteration
#define WPB 16           // warps per block (msg/qkvg)
#define LN_EPS 1e-3f
#define ATT_SCALE 0.35355339059327373f

typedef unsigned long long u64;

// ---------------- packed f32x2 helpers ----------------
__device__ __forceinline__ u64 ffma2(u64 a, u64 b, u64 c){
    u64 d; asm("fma.rn.f32x2 %0, %1, %2, %3;" : "=l"(d) : "l"(a), "l"(b), "l"(c)); return d;
}
__device__ __forceinline__ u64 fmul2(u64 a, u64 b){
    u64 d; asm("mul.rn.f32x2 %0, %1, %2;" : "=l"(d) : "l"(a), "l"(b)); return d;
}
__device__ __forceinline__ u64 pack2(float a, float b){
    u64 r; asm("mov.b64 %0, {%1, %2};" : "=l"(r) : "f"(a), "f"(b)); return r;
}
__device__ __forceinline__ float2 unpack2(u64 v){
    float2 f; asm("mov.b64 {%0, %1}, %2;" : "=f"(f.x), "=f"(f.y) : "l"(v)); return f;
}
__device__ __forceinline__ float psum2(u64 v){ float2 f = unpack2(v); return f.x + f.y; }

__device__ __forceinline__ float gelu_erf(float x){
    return 0.5f * x * (1.0f + erff(x * 0.70710678118654752f));
}

// ---------------- scratch ----------------
__device__ float g_agg [BB*NN*FF];
__device__ float g_q   [BB*HH*NN*DD];
__device__ float g_k   [BB*HH*NN*DD];
__device__ float g_v   [BB*HH*NN*DD];
__device__ float g_gate[BB*HH*NN*DD];
__device__ float g_att [BB*NN*FF];

// ---------------- helpers ----------------
__global__ void zero_agg_kernel(){
    int i = blockIdx.x*blockDim.x + threadIdx.x;
    if (i < BB*NN*FF) g_agg[i] = 0.0f;
}

__global__ void passthrough_kernel(const int* __restrict__ edges,
                                   const float* __restrict__ ew,
                                   const float* __restrict__ ed,
                                   float* __restrict__ out_edges,
                                   float* __restrict__ out_ew,
                                   float* __restrict__ out_ed){
    int i = blockIdx.x*blockDim.x + threadIdx.x;
    if (i < BB*EE*2){ out_edges[i] = (float)edges[i]; out_ed[i] = ed[i]; }
    if (i < BB*EE)  out_ew[i] = ew[i];
}

// ---------------- messages ----------------
__global__ __launch_bounds__(32*WPB,1)
void msg_kernel(const float* __restrict__ nodes, const float* __restrict__ efeat,
                const int* __restrict__ edges, const float* __restrict__ ew,
                const float* __restrict__ ed, const float* __restrict__ Wm,
                const float* __restrict__ bm, const float* __restrict__ gm,
                const float* __restrict__ betam, float* __restrict__ out_wm){
    extern __shared__ float smem[];
    float* sW  = smem;               // [96][KMP]
    float* sb  = sW + FF*KMP;
    float* sg  = sb + FF;
    float* sbe = sg + FF;
    float* sx  = sbe + FF;           // WPB warps * EPB * 224
    int tid = threadIdx.x;
    for (int i = tid; i < KM*FF; i += blockDim.x){
        int k = i / FF, c = i % FF;
        sW[c*KMP + k] = Wm[i];
    }
    if (tid < FF){ sb[tid]=bm[tid]; sg[tid]=gm[tid]; sbe[tid]=betam[tid]; }
    __syncthreads();

    int warp = tid >> 5, lane = tid & 31;
    float* x = sx + warp*(EPB*KM);
    int warpGlobal = blockIdx.x*WPB + warp;

    const ulonglong2* wp0 = (const ulonglong2*)(sW + (size_t)lane*KMP);
    const ulonglong2* wp1 = (const ulonglong2*)(sW + (size_t)(lane+32)*KMP);
    const ulonglong2* wp2 = (const ulonglong2*)(sW + (size_t)(lane+64)*KMP);

    for (int base = warpGlobal*EPB; base < BB*EE; base += gridDim.x*WPB*EPB){
        int dsts[EPB];
        #pragma unroll
        for (int e = 0; e < EPB; e++){
            int eid = base + e;
            int b = eid >> 14;
            int src = edges[2*eid];
            int dst = edges[2*eid+1];
            dsts[e] = (b << 10) + dst;
            const float4* ns = (const float4*)(nodes + ((size_t)((b<<10) + src))*FF);
            const float4* nd = (const float4*)(nodes + ((size_t)((b<<10) + dst))*FF);
            const float4* ep = (const float4*)(efeat + (size_t)eid*FE);
            float4* xe = (float4*)(x + e*KM);
            #pragma unroll
            for (int i0 = 0; i0 < 2; i0++){
                int i = lane + 32*i0;
                if (i < 56){
                    float4 v = (i < 24) ? ns[i] : ((i < 48) ? nd[i-24] : ep[i-48]);
                    xe[i] = v;
                }
            }
        }
        __syncwarp();

        u64 a0[EPB], a1[EPB], a2[EPB];
        #pragma unroll
        for (int e = 0; e < EPB; e++){ a0[e]=0ull; a1[e]=0ull; a2[e]=0ull; }

        #pragma unroll 4
        for (int ks = 0; ks < KM/4; ks++){
            ulonglong2 w0 = wp0[ks], w1 = wp1[ks], w2 = wp2[ks];
            #pragma unroll
            for (int e = 0; e < EPB; e++){
                ulonglong2 xv = ((const ulonglong2*)(x + e*KM))[ks];
                a0[e] = ffma2(xv.x, w0.x, a0[e]); a0[e] = ffma2(xv.y, w0.y, a0[e]);
                a1[e] = ffma2(xv.x, w1.x, a1[e]); a1[e] = ffma2(xv.y, w1.y, a1[e]);
                a2[e] = ffma2(xv.x, w2.x, a2[e]); a2[e] = ffma2(xv.y, w2.y, a2[e]);
            }
        }
        __syncwarp();

        #pragma unroll
        for (int e = 0; e < EPB; e++){
            int eid = base + e;
            float v0 = gelu_erf(psum2(a0[e]) + sb[lane]);
            float v1 = gelu_erf(psum2(a1[e]) + sb[lane+32]);
            float v2 = gelu_erf(psum2(a2[e]) + sb[lane+64]);
            float s = v0 + v1 + v2;
            #pragma unroll
            for (int off = 16; off; off >>= 1) s += __shfl_xor_sync(0xffffffffu, s, off);
            float mu = s * (1.0f/96.0f);
            float d0 = v0-mu, d1 = v1-mu, d2 = v2-mu;
            float ssq = d0*d0 + d1*d1 + d2*d2;
            #pragma unroll
            for (int off = 16; off; off >>= 1) ssq += __shfl_xor_sync(0xffffffffu, ssq, off);
            float r = rsqrtf(ssq * (1.0f/96.0f) + LN_EPS);
            float w  = ew[eid];
            float dr = ed[2*eid+1];
            float y0 = (d0*r*sg[lane]    + sbe[lane])    * w;
            float y1 = (d1*r*sg[lane+32] + sbe[lane+32]) * w;
            float y2 = (d2*r*sg[lane+64] + sbe[lane+64]) * w;
            float* ow = out_wm + (size_t)eid*FF;
            ow[lane] = y0; ow[lane+32] = y1; ow[lane+64] = y2;
            float* ap = g_agg + (size_t)dsts[e]*FF;
            atomicAdd(ap+lane,    y0*dr);
            atomicAdd(ap+lane+32, y1*dr);
            atomicAdd(ap+lane+64, y2*dr);
        }
        __syncwarp();
    }
}

// ---------------- q/k/v/gate projections (one matrix per blockIdx.y) ----------------
__global__ __launch_bounds__(32*WPB,1)
void qkvg_kernel(const float* __restrict__ nodes,
    const float* __restrict__ Wq, const float* __restrict__ bq,
    const float* __restrict__ Wk, const float* __restrict__ bk,
    const float* __restrict__ Wv, const float* __restrict__ bv,
    const float* __restrict__ Wg, const float* __restrict__ bg){
    extern __shared__ float smem[];
    float* sA  = smem;               // [96][K2P]
    float* sbA = sA + FF*K2P;
    float* sx  = sbA + FF;           // WPB * EPB * 192
    int m = blockIdx.y;
    const float* WA = (m==0)?Wq:((m==1)?Wk:((m==2)?Wv:Wg));
    const float* bA = (m==0)?bq:((m==1)?bk:((m==2)?bv:bg));
    float* outA     = (m==0)?g_q:((m==1)?g_k:((m==2)?g_v:g_gate));
    bool isGate = (m == 3);

    int tid = threadIdx.x;
    for (int i = tid; i < K2*FF; i += blockDim.x){
        int k = i / FF, c = i % FF;
        sA[c*K2P + k] = WA[i];
    }
    if (tid < FF) sbA[tid] = bA[tid];
    __syncthreads();

    int warp = tid>>5, lane = tid&31;
    float* x = sx + warp*(EPB*K2);
    int warpGlobal = blockIdx.x*WPB + warp;

    const ulonglong2* wp0 = (const ulonglong2*)(sA + (size_t)lane*K2P);
    const ulonglong2* wp1 = (const ulonglong2*)(sA + (size_t)(lane+32)*K2P);
    const ulonglong2* wp2 = (const ulonglong2*)(sA + (size_t)(lane+64)*K2P);

    for (int base = warpGlobal*EPB; base < BB*NN; base += gridDim.x*WPB*EPB){
        #pragma unroll
        for (int e = 0; e < EPB; e++){
            int idx = base + e;
            const float4* np = (const float4*)(nodes + (size_t)idx*FF);
            const float4* ap = (const float4*)(g_agg + (size_t)idx*FF);
            float4* xe = (float4*)(x + e*K2);
            #pragma unroll
            for (int i0 = 0; i0 < 2; i0++){
                int i = lane + 32*i0;
                if (i < 48){
                    float4 v = (i < 24) ? np[i] : ap[i-24];
                    xe[i] = v;
                }
            }
        }
        __syncwarp();

        u64 a0[EPB], a1[EPB], a2[EPB];
        #pragma unroll
        for (int e = 0; e < EPB; e++){ a0[e]=0ull; a1[e]=0ull; a2[e]=0ull; }

        #pragma unroll 4
        for (int ks = 0; ks < K2/4; ks++){
            ulonglong2 w0 = wp0[ks], w1 = wp1[ks], w2 = wp2[ks];
            #pragma unroll
            for (int e = 0; e < EPB; e++){
                ulonglong2 xv = ((const ulonglong2*)(x + e*K2))[ks];
                a0[e] = ffma2(xv.x, w0.x, a0[e]); a0[e] = ffma2(xv.y, w0.y, a0[e]);
                a1[e] = ffma2(xv.x, w1.x, a1[e]); a1[e] = ffma2(xv.y, w1.y, a1[e]);
                a2[e] = ffma2(xv.x, w2.x, a2[e]); a2[e] = ffma2(xv.y, w2.y, a2[e]);
            }
        }
        __syncwarp();

        #pragma unroll
        for (int e = 0; e < EPB; e++){
            int idx = base + e;
            int b = idx >> 10, n = idx & (NN-1);
            float vals[3];
            vals[0] = psum2(a0[e]) + sbA[lane];
            vals[1] = psum2(a1[e]) + sbA[lane+32];
            vals[2] = psum2(a2[e]) + sbA[lane+64];
            #pragma unroll
            for (int c = 0; c < 3; c++){
                int col = lane + 32*c;
                int h = col >> 3, dl = col & 7;
                size_t off = ((size_t)(b*HH + h)*NN + n)*DD + dl;
                float v = vals[c];
                if (isGate) v = 1.0f/(1.0f + __expf(-v));
                outA[off] = v;
            }
        }
        __syncwarp();
    }
}

// ---------------- attention: lane-local online softmax, 4 rows/warp, single K/V sweep ----------------
#define RPW 4
__global__ __launch_bounds__(256,2)
void attn_kernel(){
    extern __shared__ float smem[];
    float* sK = smem;                // [N][10] padded
    float* sV = smem + NN*10;
    int bh = blockIdx.x;
    int b = bh / HH, h = bh % HH;
    int tid = threadIdx.x;

    for (int j = tid; j < NN; j += 256){
        const ulonglong2* kr = (const ulonglong2*)(g_k + ((size_t)bh*NN + j)*DD);
        const ulonglong2* vr = (const ulonglong2*)(g_v + ((size_t)bh*NN + j)*DD);
        ulonglong2 k01 = kr[0], k23 = kr[1];
        ulonglong2 v01 = vr[0], v23 = vr[1];
        u64* kd = (u64*)(sK + (size_t)j*10);
        u64* vd = (u64*)(sV + (size_t)j*10);
        kd[0]=k01.x; kd[1]=k01.y; kd[2]=k23.x; kd[3]=k23.y;
        vd[0]=v01.x; vd[1]=v01.y; vd[2]=v23.x; vd[3]=v23.y;
    }
    __syncthreads();

    int warp = tid>>5, lane = tid&31;
    int rowBase = blockIdx.y*128 + warp*RPW;

    for (int p = 0; p < 4; p++){
        int r0 = rowBase + p*32;

        u64 q2[RPW][4];
        #pragma unroll
        for (int rr = 0; rr < RPW; rr++){
            const ulonglong2* qp = (const ulonglong2*)(g_q + ((size_t)bh*NN + r0+rr)*DD);
            ulonglong2 qa = qp[0], qb = qp[1];
            q2[rr][0]=qa.x; q2[rr][1]=qa.y; q2[rr][2]=qb.x; q2[rr][3]=qb.y;
        }

        // lane-local online softmax state
        float m[RPW], l[RPW];
        u64 o2[RPW][4];
        #pragma unroll
        for (int rr = 0; rr < RPW; rr++){
            m[rr] = -3.4e38f; l[rr] = 0.0f;
            o2[rr][0]=o2[rr][1]=o2[rr][2]=o2[rr][3]=0ull;
        }
        #pragma unroll 4
        for (int t = 0; t < 32; t++){
            int j = t*32 + lane;
            const u64* kj = (const u64*)(sK + (size_t)j*10);
            const u64* vj = (const u64*)(sV + (size_t)j*10);
            u64 k0=kj[0], k1=kj[1], k2=kj[2], k3=kj[3];
            u64 v0=vj[0], v1=vj[1], v2=vj[2], v3=vj[3];
            #pragma unroll
            for (int rr = 0; rr < RPW; rr++){
                u64 acc = fmul2(q2[rr][0], k0);
                acc = ffma2(q2[rr][1], k1, acc);
                acc = ffma2(q2[rr][2], k2, acc);
                acc = ffma2(q2[rr][3], k3, acc);
                float s = psum2(acc) * ATT_SCALE;
                float mn  = fmaxf(m[rr], s);
                float fac = __expf(m[rr] - mn);   // 0 when m was -inf
                float pe  = __expf(s - mn);
                m[rr] = mn;
                l[rr] = l[rr]*fac + pe;
                u64 fc2 = pack2(fac, fac);
                u64 p2  = pack2(pe, pe);
                o2[rr][0] = ffma2(p2, v0, fmul2(fc2, o2[rr][0]));
                o2[rr][1] = ffma2(p2, v1, fmul2(fc2, o2[rr][1]));
                o2[rr][2] = ffma2(p2, v2, fmul2(fc2, o2[rr][2]));
                o2[rr][3] = ffma2(p2, v3, fmul2(fc2, o2[rr][3]));
            }
        }

        // cross-lane: global max, rescale, then sum-reduce
        #pragma unroll
        for (int rr = 0; rr < RPW; rr++){
            float M = m[rr];
            #pragma unroll
            for (int off = 16; off; off >>= 1) M = fmaxf(M, __shfl_xor_sync(0xffffffffu, M, off));
            float fac = __expf(m[rr] - M);
            l[rr] *= fac;
            u64 fc2 = pack2(fac, fac);
            #pragma unroll
            for (int k = 0; k < 4; k++) o2[rr][k] = fmul2(fc2, o2[rr][k]);

            #pragma unroll
            for (int off = 16; off; off >>= 1) l[rr] += __shfl_xor_sync(0xffffffffu, l[rr], off);
            float2 od[4];
            #pragma unroll
            for (int k = 0; k < 4; k++){
                u64 v = o2[rr][k];
                #pragma unroll
                for (int off = 16; off; off >>= 1){
                    u64 o = __shfl_xor_sync(0xffffffffu, v, off);
                    float2 va = unpack2(v), vb = unpack2(o);
                    v = pack2(va.x+vb.x, va.y+vb.y);
                }
                od[k] = unpack2(v);
            }
            if (lane < DD){
                float inv = 1.0f / l[rr];
                float val = (lane & 1) ? od[lane>>1].y : od[lane>>1].x;
                float gate = g_gate[((size_t)bh*NN + r0+rr)*DD + lane];
                g_att[((size_t)((b<<10) + r0+rr))*FF + h*DD + lane] = val*inv*gate;
            }
        }
    }
}

// ---------------- output: LN(GELU(att @ Wo + bo)) ----------------
__global__ __launch_bounds__(512,1)
void out_kernel(const float* __restrict__ Wo, const float* __restrict__ bo,
                const float* __restrict__ gu, const float* __restrict__ betau,
                float* __restrict__ out){
    __shared__ float sW[FF*FF];
    __shared__ float sb[FF], sg[FF], sbe[FF];
    __shared__ float sx[16*FF];
    int tid = threadIdx.x;
    for (int i = tid; i < FF*FF; i += blockDim.x) sW[i] = Wo[i];
    if (tid < FF){ sb[tid]=bo[tid]; sg[tid]=gu[tid]; sbe[tid]=betau[tid]; }
    __syncthreads();

    int warp = tid>>5, lane = tid&31;
    float* x = sx + warp*FF;
    for (int idx = blockIdx.x*16 + warp; idx < BB*NN; idx += gridDim.x*16){
        const float* ap = g_att + (size_t)idx*FF;
        for (int i = lane; i < FF; i += 32) x[i] = ap[i];
        __syncwarp();
        float a0 = sb[lane], a1 = sb[lane+32], a2 = sb[lane+64];
        #pragma unroll 4
        for (int k = 0; k < FF; k++){
            float xv = x[k];
            a0 = fmaf(xv, sW[k*FF+lane],    a0);
            a1 = fmaf(xv, sW[k*FF+lane+32], a1);
            a2 = fmaf(xv, sW[k*FF+lane+64], a2);
        }
        a0 = gelu_erf(a0); a1 = gelu_erf(a1); a2 = gelu_erf(a2);
        float s = a0 + a1 + a2;
        #pragma unroll
        for (int off = 16; off; off >>= 1) s += __shfl_xor_sync(0xffffffffu, s, off);
        float mu = s * (1.0f/96.0f);
        float d0 = a0-mu, d1 = a1-mu, d2 = a2-mu;
        float ssq = d0*d0 + d1*d1 + d2*d2;
        #pragma unroll
        for (int off = 16; off; off >>= 1) ssq += __shfl_xor_sync(0xffffffffu, ssq, off);
        float r = rsqrtf(ssq * (1.0f/96.0f) + LN_EPS);
        float* op = out + (size_t)idx*FF;
        op[lane]    = d0*r*sg[lane]    + sbe[lane];
        op[lane+32] = d1*r*sg[lane+32] + sbe[lane+32];
        op[lane+64] = d2*r*sg[lane+64] + sbe[lane+64];
        __syncwarp();
    }
}

// ---------------- launch ----------------
extern "C" void kernel_launch(void* const* d_in, const int* in_sizes, int n_in,
                              void* d_out, int out_size){
    const float* nodes = (const float*)d_in[0];
    const float* efeat = (const float*)d_in[1];
    const int*   edges = (const int*)  d_in[2];
    const float* ew    = (const float*)d_in[3];
    const float* ed    = (const float*)d_in[4];
    const float* Wm    = (const float*)d_in[5];
    const float* bm    = (const float*)d_in[6];
    const float* gm    = (const float*)d_in[7];
    const float* betam = (const float*)d_in[8];
    const float* Wq=(const float*)d_in[9],  *bq=(const float*)d_in[10];
    const float* Wk=(const float*)d_in[11], *bk=(const float*)d_in[12];
    const float* Wv=(const float*)d_in[13], *bv=(const float*)d_in[14];
    const float* Wg=(const float*)d_in[15], *bg=(const float*)d_in[16];
    const float* Wo=(const float*)d_in[17], *bo=(const float*)d_in[18];
    const float* gu=(const float*)d_in[19], *betau=(const float*)d_in[20];
    float* out = (float*)d_out;

    const size_t OFF_WM    = (size_t)BB*NN*FF;
    const size_t OFF_EDGES = OFF_WM + (size_t)BB*EE*FF;
    const size_t OFF_EW    = OFF_EDGES + (size_t)BB*EE*2;
    const size_t OFF_ED    = OFF_EW + (size_t)BB*EE;

    const int MSG_SMEM  = (FF*KMP + 3*FF + WPB*EPB*KM)*4;   // 203392 B
    const int QKVG_SMEM = (FF*K2P + FF + WPB*EPB*K2)*4;     // 173952 B
    const int ATTN_SMEM = 2*NN*10*4;                        // 81920 B
    cudaFuncSetAttribute(msg_kernel,  cudaFuncAttributeMaxDynamicSharedMemorySize, MSG_SMEM);
    cudaFuncSetAttribute(qkvg_kernel, cudaFuncAttributeMaxDynamicSharedMemorySize, QKVG_SMEM);
    cudaFuncSetAttribute(attn_kernel, cudaFuncAttributeMaxDynamicSharedMemorySize, ATTN_SMEM);

    zero_agg_kernel<<<(BB*NN*FF+255)/256, 256>>>();
    passthrough_kernel<<<(BB*EE*2+255)/256, 256>>>(edges, ew, ed,
                                                   out+OFF_EDGES, out+OFF_EW, out+OFF_ED);
    msg_kernel<<<148, 32*WPB, MSG_SMEM>>>(nodes, efeat, edges, ew, ed,
                                          Wm, bm, gm, betam, out+OFF_WM);
    qkvg_kernel<<<dim3(37,4), 32*WPB, QKVG_SMEM>>>(nodes, Wq,bq, Wk,bk, Wv,bv, Wg,bg);
    attn_kernel<<<dim3(BB*HH,8), 256, ATTN_SMEM>>>();
    out_kernel<<<148, 512>>>(Wo, bo, gu, betau, out);
}